// round 9
// baseline (speedup 1.0000x reference)
#include <cuda_runtime.h>
#include <cuda_bf16.h>
#include <cstdint>

#define BB 4
#define C 128
#define CO 256
#define H 128
#define W 128
#define HP 130
#define WP 130
#define HPWP (HP*WP)
#define KTOT 1152        // C*9, tap-major: k = n*128 + c

// ---------------- device scratch (static only, per harness rules) ----------
__device__ float g_xpad[BB*C*HP*WP];                 // padded input
__device__ float g_off[BB*H*W*2*9];                  // offsets [b][h][w][18]
__device__ __nv_bfloat16 g_wBhi[CO*KTOT];            // weights hi, [o][n*128+c]
__device__ __nv_bfloat16 g_wBlo[CO*KTOT];            // weights lo
__device__ float g_sums[2*CO];                       // BN partial sum / sumsq

// ---------------- PTX helpers ----------------------------------------------
__device__ __forceinline__ uint32_t smem_u32(const void* p) {
    uint32_t a;
    asm("{ .reg .u64 t; cvta.to.shared.u64 t, %1; cvt.u32.u64 %0, t; }" : "=r"(a) : "l"(p));
    return a;
}
__device__ __forceinline__ void mma_bf16(float* d, const uint32_t* a, const uint32_t* b) {
    asm volatile("mma.sync.aligned.m16n8k16.row.col.f32.bf16.bf16.f32 "
        "{%0,%1,%2,%3}, {%4,%5,%6,%7}, {%8,%9}, {%0,%1,%2,%3};"
        : "+f"(d[0]), "+f"(d[1]), "+f"(d[2]), "+f"(d[3])
        : "r"(a[0]), "r"(a[1]), "r"(a[2]), "r"(a[3]), "r"(b[0]), "r"(b[1]));
}
__device__ __forceinline__ void ldsm4(uint32_t* r, uint32_t addr) {
    asm volatile("ldmatrix.sync.aligned.m8n8.x4.shared.b16 {%0,%1,%2,%3}, [%4];"
        : "=r"(r[0]), "=r"(r[1]), "=r"(r[2]), "=r"(r[3]) : "r"(addr));
}
__device__ __forceinline__ void cp16(uint32_t dst, const void* src) {
    asm volatile("cp.async.cg.shared.global [%0], [%1], 16;" :: "r"(dst), "l"(src));
}
#define CP_COMMIT() asm volatile("cp.async.commit_group;" ::: "memory")
#define CP_WAIT0()  asm volatile("cp.async.wait_group 0;" ::: "memory")

// ---------------------------------------------------------------------------
__global__ void pad_kernel(const float* __restrict__ x) {
    int idx = blockIdx.x*blockDim.x + threadIdx.x;
    if (idx < 2*CO) g_sums[idx] = 0.f;               // zero BN accumulators
    if (idx >= BB*C*HP*WP) return;
    int j = idx % WP; int t = idx / WP; int i = t % HP; int bc = t / HP;
    float v = 0.f;
    if (i >= 1 && i <= H && j >= 1 && j <= W)
        v = x[(bc*H + (i-1))*W + (j-1)];
    g_xpad[idx] = v;
}

// split weights to bf16 hi/lo, reorder to tap-major k = n*128 + c
__global__ void wprep_kernel(const float* __restrict__ w) {
    int idx = blockIdx.x*blockDim.x + threadIdx.x;
    if (idx >= CO*KTOT) return;
    int o = idx / KTOT, r = idx % KTOT;
    int n = r >> 7, c = r & 127;
    float v = w[(o*C + c)*9 + n];
    __nv_bfloat16 hi = __float2bfloat16(v);
    __nv_bfloat16 lo = __float2bfloat16(v - __bfloat162float(hi));
    g_wBhi[idx] = hi;
    g_wBlo[idx] = lo;
}

// ---------------------------------------------------------------------------
// Offset conv: 18 out channels, 3x3, pad 1. One thread per (b, 2 h-rows, w).
__global__ __launch_bounds__(128) void offconv_kernel(
        const float* __restrict__ pw, const float* __restrict__ pb) {
    __shared__ float s_pw[576*20];
    int b = blockIdx.x / (H/2), h0 = (blockIdx.x % (H/2))*2;
    int w = threadIdx.x;
    float acc0[18], acc1[18];
    #pragma unroll
    for (int j = 0; j < 18; j++) { acc0[j] = pb[j]; acc1[j] = pb[j]; }

    for (int cc = 0; cc < 2; cc++) {
        __syncthreads();
        for (int i = threadIdx.x; i < 576*18; i += 128) {
            int k = i / 18, j = i - (i/18)*18;
            s_pw[k*20 + j] = pw[j*KTOT + cc*576 + k];
        }
        __syncthreads();
        for (int k = 0; k < 576; k++) {
            int c = cc*64 + k/9;
            int kidx = k - (k/9)*9;
            const float* xp = g_xpad + ((size_t)(b*C + c)*HP + h0 + kidx/3)*WP + w + kidx%3;
            float xv0 = xp[0];
            float xv1 = xp[WP];
            const float4* r = (const float4*)(s_pw + k*20);
            float4 a0 = r[0], a1 = r[1], a2 = r[2], a3 = r[3];
            float b0 = s_pw[k*20+16], b1 = s_pw[k*20+17];
            acc0[0]+=xv0*a0.x; acc0[1]+=xv0*a0.y; acc0[2]+=xv0*a0.z; acc0[3]+=xv0*a0.w;
            acc0[4]+=xv0*a1.x; acc0[5]+=xv0*a1.y; acc0[6]+=xv0*a1.z; acc0[7]+=xv0*a1.w;
            acc0[8]+=xv0*a2.x; acc0[9]+=xv0*a2.y; acc0[10]+=xv0*a2.z; acc0[11]+=xv0*a2.w;
            acc0[12]+=xv0*a3.x; acc0[13]+=xv0*a3.y; acc0[14]+=xv0*a3.z; acc0[15]+=xv0*a3.w;
            acc0[16]+=xv0*b0;  acc0[17]+=xv0*b1;
            acc1[0]+=xv1*a0.x; acc1[1]+=xv1*a0.y; acc1[2]+=xv1*a0.z; acc1[3]+=xv1*a0.w;
            acc1[4]+=xv1*a1.x; acc1[5]+=xv1*a1.y; acc1[6]+=xv1*a1.z; acc1[7]+=xv1*a1.w;
            acc1[8]+=xv1*a2.x; acc1[9]+=xv1*a2.y; acc1[10]+=xv1*a2.z; acc1[11]+=xv1*a2.w;
            acc1[12]+=xv1*a3.x; acc1[13]+=xv1*a3.y; acc1[14]+=xv1*a3.z; acc1[15]+=xv1*a3.w;
            acc1[16]+=xv1*b0;  acc1[17]+=xv1*b1;
        }
    }
    float* op0 = g_off + (((size_t)(b*H + h0)*W) + w)*18;
    float* op1 = op0 + (size_t)W*18;
    #pragma unroll
    for (int j = 0; j < 18; j++) { op0[j] = acc0[j]; op1[j] = acc1[j]; }
}

// ---------------------------------------------------------------------------
// Deformable implicit GEMM, mma.sync m16n8k16 bf16 hi/lo split (3 products).
// CTA 512 thr, tile M=128 pos x N=256 ch, K=1152 in 72 half-chunks of k=16.
// Gather: warp = 32 consecutive positions (lanes) x 4 channels (warp group).
// Pipeline: wait B(hc) -> sync -> store A(hc+1), issue B(hc+1), LDG raw(hc+2)
//           -> MMA(hc). smem double-buffered; rows stride 48B.
#define NHC 72
#define ARS 48
#define S_AH 0
#define S_AL 6144
#define S_BH 12288
#define S_BL 24576
#define STG  36864
#define SMEM_DYN (2*STG)

__global__ __launch_bounds__(512, 1) void deform_mma(float* __restrict__ out) {
    extern __shared__ char sm[];
    const int tid  = threadIdx.x;
    const int lane = tid & 31;
    const int wid  = tid >> 5;
    const int wm   = wid & 3;        // MMA pos group (32 each)
    const int wn   = wid >> 2;       // MMA channel group (64 each)
    const int b    = blockIdx.y;
    const int h    = blockIdx.x;
    const int pos  = (wid & 3)*32 + lane;   // gather position (0..127)
    const int cg   = wid >> 2;              // gather channel group (4 ch)
    const uint32_t sbase = smem_u32(sm);

    // ldmatrix lane byte-offsets (within Ah / Bh planes)
    const uint32_t aoff = (uint32_t)((wm*32 + (lane & 7) + ((lane >> 3) & 1)*8)*ARS + (lane >> 4)*16);
    const uint32_t boff = (uint32_t)((wn*64 + (lane & 7) + (lane >> 4)*8)*ARS + ((lane >> 3) & 1)*16);

    float acc[2][8][4];
    #pragma unroll
    for (int mi = 0; mi < 2; mi++)
        #pragma unroll
        for (int nt = 0; nt < 8; nt++)
            #pragma unroll
            for (int j = 0; j < 4; j++) acc[mi][nt][j] = 0.f;

    int i00 = 0, i01 = 0, i10 = 0, i11 = 0;
    float gg0 = 0.f, gg1 = 0.f, gg2 = 0.f, gg3 = 0.f;
    float raw[16];

    auto calc_params = [&](int n) {
        const float* offp = g_off + ((size_t)((b*H + h)*W + pos))*18;
        float ox = offp[n], oy = offp[9 + n];
        float px = (float)(h + n/3) + ox;
        float py = (float)(pos + n%3) + oy;
        float fx = floorf(px), fy = floorf(py);
        float x0 = fminf(fmaxf(fx,     0.f), 129.f);
        float x1 = fminf(fmaxf(fx+1.f, 0.f), 129.f);
        float y0 = fminf(fmaxf(fy,     0.f), 129.f);
        float y1 = fminf(fmaxf(fy+1.f, 0.f), 129.f);
        float pcx = fminf(fmaxf(px, 0.f), 129.f);
        float pcy = fminf(fmaxf(py, 0.f), 129.f);
        float wx0 = 1.f + (x0 - pcx), wx1 = 1.f - (x1 - pcx);
        float wy0 = 1.f + (y0 - pcy), wy1 = 1.f - (y1 - pcy);
        int ix0 = (int)x0 * WP, ix1 = (int)x1 * WP;
        int iy0 = (int)y0,      iy1 = (int)y1;
        i00 = ix0 + iy0; i01 = ix0 + iy1; i10 = ix1 + iy0; i11 = ix1 + iy1;
        gg0 = wx0*wy0; gg1 = wx1*wy1; gg2 = wx0*wy1; gg3 = wx1*wy0;
    };
    auto prefetch = [&](int hc2) {
        int ch = (hc2 & 7) * 16 + cg*4;
        const float* __restrict__ base = g_xpad + ((size_t)(b*C + ch))*HPWP;
        #pragma unroll
        for (int cc = 0; cc < 4; cc++) {
            const float* __restrict__ Xp = base + (size_t)cc*HPWP;
            raw[cc*4+0] = Xp[i00];
            raw[cc*4+1] = Xp[i11];
            raw[cc*4+2] = Xp[i01];
            raw[cc*4+3] = Xp[i10];
        }
    };
    auto store_A = [&](int hn) {
        char* st = sm + (hn & 1)*STG;
        float v0 = gg0*raw[0]  + gg1*raw[1]  + gg2*raw[2]  + gg3*raw[3];
        float v1 = gg0*raw[4]  + gg1*raw[5]  + gg2*raw[6]  + gg3*raw[7];
        float v2 = gg0*raw[8]  + gg1*raw[9]  + gg2*raw[10] + gg3*raw[11];
        float v3 = gg0*raw[12] + gg1*raw[13] + gg2*raw[14] + gg3*raw[15];
        __nv_bfloat16 h0 = __float2bfloat16(v0), h1 = __float2bfloat16(v1);
        __nv_bfloat16 h2 = __float2bfloat16(v2), h3 = __float2bfloat16(v3);
        __nv_bfloat16 l0 = __float2bfloat16(v0 - __bfloat162float(h0));
        __nv_bfloat16 l1 = __float2bfloat16(v1 - __bfloat162float(h1));
        __nv_bfloat16 l2 = __float2bfloat16(v2 - __bfloat162float(h2));
        __nv_bfloat16 l3 = __float2bfloat16(v3 - __bfloat162float(h3));
        uint32_t hp0 = (uint32_t)*(unsigned short*)&h0 | ((uint32_t)*(unsigned short*)&h1 << 16);
        uint32_t hp1 = (uint32_t)*(unsigned short*)&h2 | ((uint32_t)*(unsigned short*)&h3 << 16);
        uint32_t lp0 = (uint32_t)*(unsigned short*)&l0 | ((uint32_t)*(unsigned short*)&l1 << 16);
        uint32_t lp1 = (uint32_t)*(unsigned short*)&l2 | ((uint32_t)*(unsigned short*)&l3 << 16);
        *(uint2*)(st + S_AH + pos*ARS + cg*8) = make_uint2(hp0, hp1);
        *(uint2*)(st + S_AL + pos*ARS + cg*8) = make_uint2(lp0, lp1);
    };
    auto issue_B = [&](int hn) {
        uint32_t stu = sbase + (hn & 1)*STG;
        int o = tid >> 1, seg = tid & 1;
        int n = hn >> 3, ch = (hn & 7)*16;
        size_t srcoff = (size_t)o*KTOT + n*128 + ch + seg*8;
        cp16(stu + S_BH + o*ARS + seg*16, g_wBhi + srcoff);
        cp16(stu + S_BL + o*ARS + seg*16, g_wBlo + srcoff);
        CP_COMMIT();
    };

    // ---- prologue ----
    calc_params(0);
    prefetch(0);
    store_A(0);
    issue_B(0);
    prefetch(1);          // tap(1) == tap(0), params still valid

    for (int hc = 0; hc < NHC; hc++) {
        const uint32_t stu = sbase + (hc & 1)*STG;

        CP_WAIT0();
        __syncthreads();

        if (hc + 1 < NHC) {
            store_A(hc + 1);      // uses raw(hc+1) + params(tap(hc+1))
            issue_B(hc + 1);
            int hn2 = hc + 2;
            if (hn2 < NHC) {
                if ((hn2 & 7) == 0) calc_params(hn2 >> 3);
                prefetch(hn2);    // hidden under MMA below
            }
        }

        // ---- MMA on stage hc&1 ----
        uint32_t ah[2][4], al[2][4];
        ldsm4(ah[0], stu + S_AH + aoff);
        ldsm4(ah[1], stu + S_AH + aoff + 16*ARS);
        ldsm4(al[0], stu + S_AL + aoff);
        ldsm4(al[1], stu + S_AL + aoff + 16*ARS);
        #pragma unroll
        for (int j = 0; j < 4; j++) {
            uint32_t bh[4], bl[4];
            ldsm4(bh, stu + S_BH + boff + j*16*ARS);
            ldsm4(bl, stu + S_BL + boff + j*16*ARS);
            #pragma unroll
            for (int mi = 0; mi < 2; mi++) {
                mma_bf16(acc[mi][2*j],   ah[mi], bh);
                mma_bf16(acc[mi][2*j],   ah[mi], bl);
                mma_bf16(acc[mi][2*j],   al[mi], bh);
                mma_bf16(acc[mi][2*j+1], ah[mi], bh + 2);
                mma_bf16(acc[mi][2*j+1], ah[mi], bl + 2);
                mma_bf16(acc[mi][2*j+1], al[mi], bh + 2);
            }
        }
    }

    __syncthreads();

    // ---- epilogue: transpose via smem; fused BN partial sums ----
    float* sepi = (float*)sm;        // [64 ch][129 pos] fp32 = 33 KB
    const int r  = lane >> 2;
    const int tq = lane & 3;
    for (int qt = 0; qt < 4; qt++) {
        if (wn == qt) {
            #pragma unroll
            for (int mi = 0; mi < 2; mi++) {
                int pos0 = wm*32 + mi*16 + r;
                #pragma unroll
                for (int nt = 0; nt < 8; nt++) {
                    int ch0 = nt*8 + tq*2;
                    sepi[(ch0  )*129 + pos0    ] = acc[mi][nt][0];
                    sepi[(ch0+1)*129 + pos0    ] = acc[mi][nt][1];
                    sepi[(ch0  )*129 + pos0 + 8] = acc[mi][nt][2];
                    sepi[(ch0+1)*129 + pos0 + 8] = acc[mi][nt][3];
                }
            }
        }
        __syncthreads();
        {
            int ri = tid >> 3, j = tid & 7;          // 64 rows x 8 segs of 16
            int o = qt*64 + ri;
            const float* src = sepi + ri*129 + j*16;
            float* dst = out + (((size_t)b*CO + o)*H + h)*W + j*16;
            float s1 = 0.f, s2 = 0.f;
            #pragma unroll
            for (int k4 = 0; k4 < 4; k4++) {
                float4 v = make_float4(src[k4*4+0], src[k4*4+1], src[k4*4+2], src[k4*4+3]);
                *(float4*)(dst + k4*4) = v;
                s1 += v.x + v.y + v.z + v.w;
                s2 += v.x*v.x + v.y*v.y + v.z*v.z + v.w*v.w;
            }
            // reduce over the 8 j-lanes (contiguous within warp)
            #pragma unroll
            for (int m = 1; m < 8; m <<= 1) {
                s1 += __shfl_xor_sync(0xffffffffu, s1, m);
                s2 += __shfl_xor_sync(0xffffffffu, s2, m);
            }
            if (j == 0) {
                atomicAdd(&g_sums[o], s1);
                atomicAdd(&g_sums[CO + o], s2);
            }
        }
        __syncthreads();
    }
}

// ---------------------------------------------------------------------------
__global__ void bn_apply(float* __restrict__ out,
                         const float* __restrict__ gamma,
                         const float* __restrict__ beta) {
    int idx = blockIdx.x*blockDim.x + threadIdx.x;
    const int total4 = BB*CO*H*W/4;
    if (idx >= total4) return;
    int o = ((idx*4) / (H*W)) % CO;
    const float inv = 1.f / (float)(BB*H*W);
    float mean = g_sums[o] * inv;
    float var  = g_sums[CO + o] * inv - mean*mean;
    float sc = gamma[o] * rsqrtf(var + 1e-5f);
    float sh = beta[o] - mean*sc;
    float4 v = ((float4*)out)[idx];
    v.x = v.x*sc + sh; v.x = v.x >= 0.f ? v.x : 0.1f*v.x;
    v.y = v.y*sc + sh; v.y = v.y >= 0.f ? v.y : 0.1f*v.y;
    v.z = v.z*sc + sh; v.z = v.z >= 0.f ? v.z : 0.1f*v.z;
    v.w = v.w*sc + sh; v.w = v.w >= 0.f ? v.w : 0.1f*v.w;
    ((float4*)out)[idx] = v;
}

// ---------------------------------------------------------------------------
extern "C" void kernel_launch(void* const* d_in, const int* in_sizes, int n_in,
                              void* d_out, int out_size) {
    const float* x      = (const float*)d_in[0];
    const float* p_w    = (const float*)d_in[1];
    const float* p_b    = (const float*)d_in[2];
    const float* w_conv = (const float*)d_in[3];
    const float* gamma  = (const float*)d_in[4];
    const float* beta   = (const float*)d_in[5];
    float* out = (float*)d_out;

    cudaFuncSetAttribute(deform_mma, cudaFuncAttributeMaxDynamicSharedMemorySize, SMEM_DYN);

    pad_kernel    <<<(BB*C*HP*WP + 255)/256, 256>>>(x);
    wprep_kernel  <<<(CO*KTOT + 255)/256, 256>>>(w_conv);
    offconv_kernel<<<BB*H/2, 128>>>(p_w, p_b);
    deform_mma    <<<dim3(H, BB), 512, SMEM_DYN>>>(out);
    bn_apply      <<<(BB*CO*H*W/4 + 255)/256, 256>>>(out, gamma, beta);
}

// round 12
// speedup vs baseline: 1.0893x; 1.0893x over previous
#include <cuda_runtime.h>
#include <cuda_bf16.h>
#include <cstdint>

#define BB 4
#define C 128
#define CO 256
#define H 128
#define W 128
#define HP 130
#define WP 130
#define HPWP (HP*WP)
#define KTOT 1152        // C*9, tap-major: k = n*128 + c

// ---------------- device scratch (static only, per harness rules) ----------
__device__ float g_xpad[BB*C*HP*WP];                 // padded input
__device__ float g_off[BB*H*W*2*9];                  // offsets [b][h][w][18]
__device__ __nv_bfloat16 g_wBhi[CO*KTOT];            // weights hi, [o][n*128+c]
__device__ __nv_bfloat16 g_wBlo[CO*KTOT];            // weights lo
__device__ float g_sums[2*CO];                       // BN partial sum / sumsq

// ---------------- PTX helpers ----------------------------------------------
__device__ __forceinline__ uint32_t smem_u32(const void* p) {
    uint32_t a;
    asm("{ .reg .u64 t; cvta.to.shared.u64 t, %1; cvt.u32.u64 %0, t; }" : "=r"(a) : "l"(p));
    return a;
}
__device__ __forceinline__ void mma_bf16(float* d, const uint32_t* a, const uint32_t* b) {
    asm volatile("mma.sync.aligned.m16n8k16.row.col.f32.bf16.bf16.f32 "
        "{%0,%1,%2,%3}, {%4,%5,%6,%7}, {%8,%9}, {%0,%1,%2,%3};"
        : "+f"(d[0]), "+f"(d[1]), "+f"(d[2]), "+f"(d[3])
        : "r"(a[0]), "r"(a[1]), "r"(a[2]), "r"(a[3]), "r"(b[0]), "r"(b[1]));
}
__device__ __forceinline__ void ldsm4(uint32_t* r, uint32_t addr) {
    asm volatile("ldmatrix.sync.aligned.m8n8.x4.shared.b16 {%0,%1,%2,%3}, [%4];"
        : "=r"(r[0]), "=r"(r[1]), "=r"(r[2]), "=r"(r[3]) : "r"(addr));
}
__device__ __forceinline__ void cp16(uint32_t dst, const void* src) {
    asm volatile("cp.async.cg.shared.global [%0], [%1], 16;" :: "r"(dst), "l"(src));
}
#define CP_COMMIT() asm volatile("cp.async.commit_group;" ::: "memory")
#define CP_WAIT0()  asm volatile("cp.async.wait_group 0;" ::: "memory")

// ---------------------------------------------------------------------------
__global__ void pad_kernel(const float* __restrict__ x) {
    int idx = blockIdx.x*blockDim.x + threadIdx.x;
    if (idx < 2*CO) g_sums[idx] = 0.f;               // zero BN accumulators
    if (idx >= BB*C*HP*WP) return;
    int j = idx % WP; int t = idx / WP; int i = t % HP; int bc = t / HP;
    float v = 0.f;
    if (i >= 1 && i <= H && j >= 1 && j <= W)
        v = x[(bc*H + (i-1))*W + (j-1)];
    g_xpad[idx] = v;
}

// split weights to bf16 hi/lo, reorder to tap-major k = n*128 + c
__global__ void wprep_kernel(const float* __restrict__ w) {
    int idx = blockIdx.x*blockDim.x + threadIdx.x;
    if (idx >= CO*KTOT) return;
    int o = idx / KTOT, r = idx % KTOT;
    int n = r >> 7, c = r & 127;
    float v = w[(o*C + c)*9 + n];
    __nv_bfloat16 hi = __float2bfloat16(v);
    __nv_bfloat16 lo = __float2bfloat16(v - __bfloat162float(hi));
    g_wBhi[idx] = hi;
    g_wBlo[idx] = lo;
}

// ---------------------------------------------------------------------------
// Offset conv: 18 out channels, 3x3, pad 1. One thread per (b,h,w). (R6 version)
__global__ __launch_bounds__(128) void offconv_kernel(
        const float* __restrict__ pw, const float* __restrict__ pb) {
    __shared__ float s_pw[576*20];
    int b = blockIdx.x / H, h = blockIdx.x % H;
    int w = threadIdx.x;
    float acc[18];
    #pragma unroll
    for (int j = 0; j < 18; j++) acc[j] = pb[j];

    for (int cc = 0; cc < 2; cc++) {
        __syncthreads();
        for (int i = threadIdx.x; i < 576*18; i += 128) {
            int k = i / 18, j = i - (i/18)*18;
            s_pw[k*20 + j] = pw[j*KTOT + cc*576 + k];
        }
        __syncthreads();
        for (int k = 0; k < 576; k++) {
            int c = cc*64 + k/9;
            int kidx = k - (k/9)*9;
            float xv = g_xpad[((b*C + c)*HP + h + kidx/3)*WP + w + kidx%3];
            const float4* r = (const float4*)(s_pw + k*20);
            float4 a0 = r[0], a1 = r[1], a2 = r[2], a3 = r[3];
            float b0 = s_pw[k*20+16], b1 = s_pw[k*20+17];
            acc[0]  += xv*a0.x; acc[1]  += xv*a0.y; acc[2]  += xv*a0.z; acc[3]  += xv*a0.w;
            acc[4]  += xv*a1.x; acc[5]  += xv*a1.y; acc[6]  += xv*a1.z; acc[7]  += xv*a1.w;
            acc[8]  += xv*a2.x; acc[9]  += xv*a2.y; acc[10] += xv*a2.z; acc[11] += xv*a2.w;
            acc[12] += xv*a3.x; acc[13] += xv*a3.y; acc[14] += xv*a3.z; acc[15] += xv*a3.w;
            acc[16] += xv*b0;   acc[17] += xv*b1;
        }
    }
    float* op = g_off + (((b*H + h)*W) + w)*18;
    #pragma unroll
    for (int j = 0; j < 18; j++) op[j] = acc[j];
}

// ---------------------------------------------------------------------------
// Deformable implicit GEMM, mma.sync m16n8k16 bf16 hi/lo split (3 products).
// CTA 256 thr (2 CTAs/SM), tile M=64 pos x N=256 ch, K=1152 in 72 half-chunks.
// Gather: warp = 32 consecutive positions x 4 channels.
// Pipeline: wait B(hc) -> sync -> store A(hc+1), issue B(hc+1), LDG raw(hc+2)
//           -> MMA(hc). smem double-buffered; rows stride 48B.
#define NHC 72
#define ARS 48
#define S_AH 0
#define S_AL 3072
#define S_BH 6144
#define S_BL 18432
#define STG  30720
#define SMEM_DYN (2*STG)

__global__ __launch_bounds__(256, 2) void deform_mma(float* __restrict__ out) {
    extern __shared__ char sm[];
    const int tid  = threadIdx.x;
    const int lane = tid & 31;
    const int wid  = tid >> 5;       // 0..7
    const int wm   = wid & 1;        // MMA pos group (32 each)
    const int wn   = wid >> 1;       // MMA channel group (64 each)
    const int b    = blockIdx.y;
    const int h    = blockIdx.x >> 1;
    const int w0   = (blockIdx.x & 1) * 64;
    const int pos  = (wid & 1)*32 + lane;   // gather position (0..63)
    const int cg   = wid >> 1;              // gather channel group (4 ch)
    const uint32_t sbase = smem_u32(sm);

    // ldmatrix lane byte-offsets (within Ah / Bh planes)
    const uint32_t aoff = (uint32_t)((wm*32 + (lane & 7) + ((lane >> 3) & 1)*8)*ARS + (lane >> 4)*16);
    const uint32_t boff = (uint32_t)((wn*64 + (lane & 7) + (lane >> 4)*8)*ARS + ((lane >> 3) & 1)*16);

    float acc[2][8][4];
    #pragma unroll
    for (int mi = 0; mi < 2; mi++)
        #pragma unroll
        for (int nt = 0; nt < 8; nt++)
            #pragma unroll
            for (int j = 0; j < 4; j++) acc[mi][nt][j] = 0.f;

    int i00 = 0, i01 = 0, i10 = 0, i11 = 0;
    float gg0 = 0.f, gg1 = 0.f, gg2 = 0.f, gg3 = 0.f;
    float raw[16];

    auto calc_params = [&](int n) {
        const float* offp = g_off + ((size_t)((b*H + h)*W + w0 + pos))*18;
        float ox = offp[n], oy = offp[9 + n];
        float px = (float)(h + n/3) + ox;
        float py = (float)(w0 + pos + n%3) + oy;
        float fx = floorf(px), fy = floorf(py);
        float x0 = fminf(fmaxf(fx,     0.f), 129.f);
        float x1 = fminf(fmaxf(fx+1.f, 0.f), 129.f);
        float y0 = fminf(fmaxf(fy,     0.f), 129.f);
        float y1 = fminf(fmaxf(fy+1.f, 0.f), 129.f);
        float pcx = fminf(fmaxf(px, 0.f), 129.f);
        float pcy = fminf(fmaxf(py, 0.f), 129.f);
        float wx0 = 1.f + (x0 - pcx), wx1 = 1.f - (x1 - pcx);
        float wy0 = 1.f + (y0 - pcy), wy1 = 1.f - (y1 - pcy);
        int ix0 = (int)x0 * WP, ix1 = (int)x1 * WP;
        int iy0 = (int)y0,      iy1 = (int)y1;
        i00 = ix0 + iy0; i01 = ix0 + iy1; i10 = ix1 + iy0; i11 = ix1 + iy1;
        gg0 = wx0*wy0; gg1 = wx1*wy1; gg2 = wx0*wy1; gg3 = wx1*wy0;
    };
    auto prefetch = [&](int hc2) {
        int ch = (hc2 & 7) * 16 + cg*4;
        const float* __restrict__ base = g_xpad + ((size_t)(b*C + ch))*HPWP;
        #pragma unroll
        for (int cc = 0; cc < 4; cc++) {
            const float* __restrict__ Xp = base + (size_t)cc*HPWP;
            raw[cc*4+0] = Xp[i00];
            raw[cc*4+1] = Xp[i11];
            raw[cc*4+2] = Xp[i01];
            raw[cc*4+3] = Xp[i10];
        }
    };
    auto store_A = [&](int hn) {
        char* st = sm + (hn & 1)*STG;
        float v0 = gg0*raw[0]  + gg1*raw[1]  + gg2*raw[2]  + gg3*raw[3];
        float v1 = gg0*raw[4]  + gg1*raw[5]  + gg2*raw[6]  + gg3*raw[7];
        float v2 = gg0*raw[8]  + gg1*raw[9]  + gg2*raw[10] + gg3*raw[11];
        float v3 = gg0*raw[12] + gg1*raw[13] + gg2*raw[14] + gg3*raw[15];
        __nv_bfloat16 h0 = __float2bfloat16(v0), h1 = __float2bfloat16(v1);
        __nv_bfloat16 h2 = __float2bfloat16(v2), h3 = __float2bfloat16(v3);
        __nv_bfloat16 l0 = __float2bfloat16(v0 - __bfloat162float(h0));
        __nv_bfloat16 l1 = __float2bfloat16(v1 - __bfloat162float(h1));
        __nv_bfloat16 l2 = __float2bfloat16(v2 - __bfloat162float(h2));
        __nv_bfloat16 l3 = __float2bfloat16(v3 - __bfloat162float(h3));
        uint32_t hp0 = (uint32_t)*(unsigned short*)&h0 | ((uint32_t)*(unsigned short*)&h1 << 16);
        uint32_t hp1 = (uint32_t)*(unsigned short*)&h2 | ((uint32_t)*(unsigned short*)&h3 << 16);
        uint32_t lp0 = (uint32_t)*(unsigned short*)&l0 | ((uint32_t)*(unsigned short*)&l1 << 16);
        uint32_t lp1 = (uint32_t)*(unsigned short*)&l2 | ((uint32_t)*(unsigned short*)&l3 << 16);
        *(uint2*)(st + S_AH + pos*ARS + cg*8) = make_uint2(hp0, hp1);
        *(uint2*)(st + S_AL + pos*ARS + cg*8) = make_uint2(lp0, lp1);
    };
    auto issue_B = [&](int hn) {
        uint32_t stu = sbase + (hn & 1)*STG;
        int o = tid;                         // one row per thread
        int n = hn >> 3, ch = (hn & 7)*16;
        size_t srcoff = (size_t)o*KTOT + n*128 + ch;
        cp16(stu + S_BH + o*ARS,      g_wBhi + srcoff);
        cp16(stu + S_BH + o*ARS + 16, g_wBhi + srcoff + 8);
        cp16(stu + S_BL + o*ARS,      g_wBlo + srcoff);
        cp16(stu + S_BL + o*ARS + 16, g_wBlo + srcoff + 8);
        CP_COMMIT();
    };

    // ---- prologue ----
    calc_params(0);
    prefetch(0);
    store_A(0);
    issue_B(0);
    prefetch(1);          // tap(1) == tap(0), params still valid

    for (int hc = 0; hc < NHC; hc++) {
        const uint32_t stu = sbase + (hc & 1)*STG;

        CP_WAIT0();
        __syncthreads();

        if (hc + 1 < NHC) {
            store_A(hc + 1);      // uses raw(hc+1) + params(tap(hc+1))
            issue_B(hc + 1);
            int hn2 = hc + 2;
            if (hn2 < NHC) {
                if ((hn2 & 7) == 0) calc_params(hn2 >> 3);
                prefetch(hn2);    // hidden under MMA below
            }
        }

        // ---- MMA on stage hc&1 ----
        uint32_t ah[2][4], al[2][4];
        ldsm4(ah[0], stu + S_AH + aoff);
        ldsm4(ah[1], stu + S_AH + aoff + 16*ARS);
        ldsm4(al[0], stu + S_AL + aoff);
        ldsm4(al[1], stu + S_AL + aoff + 16*ARS);
        #pragma unroll
        for (int j = 0; j < 4; j++) {
            uint32_t bh[4], bl[4];
            ldsm4(bh, stu + S_BH + boff + j*16*ARS);
            ldsm4(bl, stu + S_BL + boff + j*16*ARS);
            #pragma unroll
            for (int mi = 0; mi < 2; mi++) {
                mma_bf16(acc[mi][2*j],   ah[mi], bh);
                mma_bf16(acc[mi][2*j],   ah[mi], bl);
                mma_bf16(acc[mi][2*j],   al[mi], bh);
                mma_bf16(acc[mi][2*j+1], ah[mi], bh + 2);
                mma_bf16(acc[mi][2*j+1], ah[mi], bl + 2);
                mma_bf16(acc[mi][2*j+1], al[mi], bh + 2);
            }
        }
    }

    __syncthreads();

    // ---- epilogue: transpose via smem; fused BN partial sums ----
    float* sepi = (float*)sm;        // [64 ch][65 pos] fp32 = 16.6 KB
    const int r  = lane >> 2;
    const int tq = lane & 3;
    for (int qt = 0; qt < 4; qt++) {
        if (wn == qt) {
            #pragma unroll
            for (int mi = 0; mi < 2; mi++) {
                int pos0 = wm*32 + mi*16 + r;
                #pragma unroll
                for (int nt = 0; nt < 8; nt++) {
                    int ch0 = nt*8 + tq*2;
                    sepi[(ch0  )*65 + pos0    ] = acc[mi][nt][0];
                    sepi[(ch0+1)*65 + pos0    ] = acc[mi][nt][1];
                    sepi[(ch0  )*65 + pos0 + 8] = acc[mi][nt][2];
                    sepi[(ch0+1)*65 + pos0 + 8] = acc[mi][nt][3];
                }
            }
        }
        __syncthreads();
        {
            int ri = tid >> 2, j = tid & 3;          // 64 rows x 4 segs of 16
            int o = qt*64 + ri;
            const float* src = sepi + ri*65 + j*16;
            float* dst = out + (((size_t)b*CO + o)*H + h)*W + w0 + j*16;
            float s1 = 0.f, s2 = 0.f;
            #pragma unroll
            for (int k4 = 0; k4 < 4; k4++) {
                float4 v = make_float4(src[k4*4+0], src[k4*4+1], src[k4*4+2], src[k4*4+3]);
                *(float4*)(dst + k4*4) = v;
                s1 += v.x + v.y + v.z + v.w;
                s2 += v.x*v.x + v.y*v.y + v.z*v.z + v.w*v.w;
            }
            // reduce over the 4 j-lanes (contiguous within warp)
            #pragma unroll
            for (int m = 1; m < 4; m <<= 1) {
                s1 += __shfl_xor_sync(0xffffffffu, s1, m);
                s2 += __shfl_xor_sync(0xffffffffu, s2, m);
            }
            if (j == 0) {
                atomicAdd(&g_sums[o], s1);
                atomicAdd(&g_sums[CO + o], s2);
            }
        }
        __syncthreads();
    }
}

// ---------------------------------------------------------------------------
__global__ void bn_apply(float* __restrict__ out,
                         const float* __restrict__ gamma,
                         const float* __restrict__ beta) {
    int idx = blockIdx.x*blockDim.x + threadIdx.x;
    const int total4 = BB*CO*H*W/4;
    if (idx >= total4) return;
    int o = ((idx*4) / (H*W)) % CO;
    const float inv = 1.f / (float)(BB*H*W);
    float mean = g_sums[o] * inv;
    float var  = g_sums[CO + o] * inv - mean*mean;
    float sc = gamma[o] * rsqrtf(var + 1e-5f);
    float sh = beta[o] - mean*sc;
    float4 v = ((float4*)out)[idx];
    v.x = v.x*sc + sh; v.x = v.x >= 0.f ? v.x : 0.1f*v.x;
    v.y = v.y*sc + sh; v.y = v.y >= 0.f ? v.y : 0.1f*v.y;
    v.z = v.z*sc + sh; v.z = v.z >= 0.f ? v.z : 0.1f*v.z;
    v.w = v.w*sc + sh; v.w = v.w >= 0.f ? v.w : 0.1f*v.w;
    ((float4*)out)[idx] = v;
}

// ---------------------------------------------------------------------------
extern "C" void kernel_launch(void* const* d_in, const int* in_sizes, int n_in,
                              void* d_out, int out_size) {
    const float* x      = (const float*)d_in[0];
    const float* p_w    = (const float*)d_in[1];
    const float* p_b    = (const float*)d_in[2];
    const float* w_conv = (const float*)d_in[3];
    const float* gamma  = (const float*)d_in[4];
    const float* beta   = (const float*)d_in[5];
    float* out = (float*)d_out;

    cudaFuncSetAttribute(deform_mma, cudaFuncAttributeMaxDynamicSharedMemorySize, SMEM_DYN);

    pad_kernel    <<<(BB*C*HP*WP + 255)/256, 256>>>(x);
    wprep_kernel  <<<(CO*KTOT + 255)/256, 256>>>(w_conv);
    offconv_kernel<<<BB*H, 128>>>(p_w, p_b);
    deform_mma    <<<dim3(H*2, BB), 256, SMEM_DYN>>>(out);
    bn_apply      <<<(BB*CO*H*W/4 + 255)/256, 256>>>(out, gamma, beta);
}

// round 14
// speedup vs baseline: 1.1943x; 1.0964x over previous
#include <cuda_runtime.h>
#include <cuda_bf16.h>
#include <cstdint>

#define BB 4
#define C 128
#define CO 256
#define H 128
#define W 128
#define HP 130
#define WP 130
#define HPWP (HP*WP)
#define KTOT 1152        // C*9, tap-major: k = n*128 + c

// ---------------- device scratch (static only, per harness rules) ----------
__device__ float g_xpad[BB*C*HP*WP];                 // padded input
__device__ float g_off[BB*H*W*2*9];                  // offsets [b][h][w][18]
__device__ __nv_bfloat16 g_wBhi[CO*KTOT];            // weights hi, [o][n*128+c]
__device__ __nv_bfloat16 g_wBlo[CO*KTOT];            // weights lo
__device__ float g_sums[2*CO];                       // BN partial sum / sumsq

// ---------------- PTX helpers ----------------------------------------------
__device__ __forceinline__ uint32_t smem_u32(const void* p) {
    uint32_t a;
    asm("{ .reg .u64 t; cvta.to.shared.u64 t, %1; cvt.u32.u64 %0, t; }" : "=r"(a) : "l"(p));
    return a;
}
__device__ __forceinline__ void mma_bf16(float* d, const uint32_t* a, const uint32_t* b) {
    asm volatile("mma.sync.aligned.m16n8k16.row.col.f32.bf16.bf16.f32 "
        "{%0,%1,%2,%3}, {%4,%5,%6,%7}, {%8,%9}, {%0,%1,%2,%3};"
        : "+f"(d[0]), "+f"(d[1]), "+f"(d[2]), "+f"(d[3])
        : "r"(a[0]), "r"(a[1]), "r"(a[2]), "r"(a[3]), "r"(b[0]), "r"(b[1]));
}
__device__ __forceinline__ void ldsm4(uint32_t* r, uint32_t addr) {
    asm volatile("ldmatrix.sync.aligned.m8n8.x4.shared.b16 {%0,%1,%2,%3}, [%4];"
        : "=r"(r[0]), "=r"(r[1]), "=r"(r[2]), "=r"(r[3]) : "r"(addr));
}
__device__ __forceinline__ void cp16(uint32_t dst, const void* src) {
    asm volatile("cp.async.cg.shared.global [%0], [%1], 16;" :: "r"(dst), "l"(src));
}
#define CP_COMMIT() asm volatile("cp.async.commit_group;" ::: "memory")
#define CP_WAIT0()  asm volatile("cp.async.wait_group 0;" ::: "memory")
#define MBAR_INIT(a, cnt) asm volatile("mbarrier.init.shared.b64 [%0], %1;" :: "r"(a), "r"(cnt) : "memory")

__device__ __forceinline__ void mbar_arrive(uint32_t a) {
    unsigned long long st;
    asm volatile("mbarrier.arrive.release.cta.shared::cta.b64 %0, [%1];"
                 : "=l"(st) : "r"(a) : "memory");
}
__device__ __forceinline__ void mbar_wait(uint32_t mbar, uint32_t parity) {
    uint32_t done;
    asm volatile("{\n .reg .pred p;\n mbarrier.try_wait.parity.acquire.cta.shared::cta.b64 p, [%1], %2;\n selp.b32 %0,1,0,p;\n}"
                 : "=r"(done) : "r"(mbar), "r"(parity) : "memory");
    if (!done) {
        asm volatile("{\n .reg .pred P1;\nWL_%=:\n mbarrier.try_wait.parity.acquire.cta.shared::cta.b64 P1, [%0], %1, 0x989680;\n @P1 bra.uni WD_%=;\n bra.uni WL_%=;\nWD_%=:\n}"
                     :: "r"(mbar), "r"(parity) : "memory");
    }
}

// ---------------------------------------------------------------------------
__global__ void pad_kernel(const float* __restrict__ x) {
    int idx = blockIdx.x*blockDim.x + threadIdx.x;
    if (idx < 2*CO) g_sums[idx] = 0.f;               // zero BN accumulators
    if (idx >= BB*C*HP*WP) return;
    int j = idx % WP; int t = idx / WP; int i = t % HP; int bc = t / HP;
    float v = 0.f;
    if (i >= 1 && i <= H && j >= 1 && j <= W)
        v = x[(bc*H + (i-1))*W + (j-1)];
    g_xpad[idx] = v;
}

// split weights to bf16 hi/lo, reorder to tap-major k = n*128 + c
__global__ void wprep_kernel(const float* __restrict__ w) {
    int idx = blockIdx.x*blockDim.x + threadIdx.x;
    if (idx >= CO*KTOT) return;
    int o = idx / KTOT, r = idx % KTOT;
    int n = r >> 7, c = r & 127;
    float v = w[(o*C + c)*9 + n];
    __nv_bfloat16 hi = __float2bfloat16(v);
    __nv_bfloat16 lo = __float2bfloat16(v - __bfloat162float(hi));
    g_wBhi[idx] = hi;
    g_wBlo[idx] = lo;
}

// ---------------------------------------------------------------------------
// Offset conv: 18 out channels, 3x3, pad 1. One thread per (b,h,w). (R6 version)
__global__ __launch_bounds__(128) void offconv_kernel(
        const float* __restrict__ pw, const float* __restrict__ pb) {
    __shared__ float s_pw[576*20];
    int b = blockIdx.x / H, h = blockIdx.x % H;
    int w = threadIdx.x;
    float acc[18];
    #pragma unroll
    for (int j = 0; j < 18; j++) acc[j] = pb[j];

    for (int cc = 0; cc < 2; cc++) {
        __syncthreads();
        for (int i = threadIdx.x; i < 576*18; i += 128) {
            int k = i / 18, j = i - (i/18)*18;
            s_pw[k*20 + j] = pw[j*KTOT + cc*576 + k];
        }
        __syncthreads();
        for (int k = 0; k < 576; k++) {
            int c = cc*64 + k/9;
            int kidx = k - (k/9)*9;
            float xv = g_xpad[((b*C + c)*HP + h + kidx/3)*WP + w + kidx%3];
            const float4* r = (const float4*)(s_pw + k*20);
            float4 a0 = r[0], a1 = r[1], a2 = r[2], a3 = r[3];
            float b0 = s_pw[k*20+16], b1 = s_pw[k*20+17];
            acc[0]  += xv*a0.x; acc[1]  += xv*a0.y; acc[2]  += xv*a0.z; acc[3]  += xv*a0.w;
            acc[4]  += xv*a1.x; acc[5]  += xv*a1.y; acc[6]  += xv*a1.z; acc[7]  += xv*a1.w;
            acc[8]  += xv*a2.x; acc[9]  += xv*a2.y; acc[10] += xv*a2.z; acc[11] += xv*a2.w;
            acc[12] += xv*a3.x; acc[13] += xv*a3.y; acc[14] += xv*a3.z; acc[15] += xv*a3.w;
            acc[16] += xv*b0;   acc[17] += xv*b1;
        }
    }
    float* op = g_off + (((b*H + h)*W) + w)*18;
    #pragma unroll
    for (int j = 0; j < 18; j++) op[j] = acc[j];
}

// ---------------------------------------------------------------------------
// Warp-specialized deformable implicit GEMM (bf16 hi/lo split, 3 products).
// CTA 512 thr: warps 0-7 producers (gather A, cp.async B), warps 8-15
// consumers (ldsm + mma, hold acc). Tile M=64 pos x N=256 ch, K=1152 in 72
// half-chunks of k=16; 3-stage mbarrier ring.
#define NHC 72
#define NST 3
#define ARS 48
#define S_AH 0
#define S_AL 3072
#define S_BH 6144
#define S_BL 18432
#define STG  30720
#define SMEM_DYN (NST*STG)

__global__ __launch_bounds__(512, 1) void deform_mma(float* __restrict__ out) {
    extern __shared__ char sm[];
    __shared__ alignas(8) unsigned long long s_mbar[2*NST];   // full[0..2], empty[3..5]

    const int tid  = threadIdx.x;
    const int lane = tid & 31;
    const int wid  = tid >> 5;       // 0..15
    const int b    = blockIdx.y;
    const int h    = blockIdx.x >> 1;
    const int w0   = (blockIdx.x & 1) * 64;
    const uint32_t sbase = smem_u32(sm);
    const uint32_t mb = smem_u32(&s_mbar[0]);

    if (tid == 0) {
        #pragma unroll
        for (int s = 0; s < NST; s++) {
            MBAR_INIT(mb + s*8, 256);            // full[s]: 256 producer threads
            MBAR_INIT(mb + (NST+s)*8, 256);      // empty[s]: 256 consumer threads
        }
    }
    __syncthreads();

    float acc[2][8][4];
    #pragma unroll
    for (int mi = 0; mi < 2; mi++)
        #pragma unroll
        for (int nt = 0; nt < 8; nt++)
            #pragma unroll
            for (int j = 0; j < 4; j++) acc[mi][nt][j] = 0.f;

    if (wid < 8) {
        // ================= PRODUCER =================
        const int pos = (wid & 1)*32 + lane;     // gather position (0..63)
        const int cg  = wid >> 1;                // gather channel group (4 ch)
        int i00 = 0, i01 = 0, i10 = 0, i11 = 0;
        float gg0 = 0.f, gg1 = 0.f, gg2 = 0.f, gg3 = 0.f;

        int s = 0, wrap = 0;
        for (int i = 0; i < NHC; i++) {
            if (i >= NST) mbar_wait(mb + (NST+s)*8, (wrap-1) & 1);

            // B tile via cp.async first (latency overlapped by gather below)
            {
                uint32_t stu = sbase + s*STG;
                int n = i >> 3, ch = (i & 7)*16;
                size_t srcoff = (size_t)tid*KTOT + n*128 + ch;
                cp16(stu + S_BH + tid*ARS,      g_wBhi + srcoff);
                cp16(stu + S_BH + tid*ARS + 16, g_wBhi + srcoff + 8);
                cp16(stu + S_BL + tid*ARS,      g_wBlo + srcoff);
                cp16(stu + S_BL + tid*ARS + 16, g_wBlo + srcoff + 8);
                CP_COMMIT();
            }

            // sampling params once per tap
            if ((i & 7) == 0) {
                int n = i >> 3;
                const float* offp = g_off + ((size_t)((b*H + h)*W + w0 + pos))*18;
                float ox = offp[n], oy = offp[9 + n];
                float px = (float)(h + n/3) + ox;
                float py = (float)(w0 + pos + n%3) + oy;
                float fx = floorf(px), fy = floorf(py);
                float x0 = fminf(fmaxf(fx,     0.f), 129.f);
                float x1 = fminf(fmaxf(fx+1.f, 0.f), 129.f);
                float y0 = fminf(fmaxf(fy,     0.f), 129.f);
                float y1 = fminf(fmaxf(fy+1.f, 0.f), 129.f);
                float pcx = fminf(fmaxf(px, 0.f), 129.f);
                float pcy = fminf(fmaxf(py, 0.f), 129.f);
                float wx0 = 1.f + (x0 - pcx), wx1 = 1.f - (x1 - pcx);
                float wy0 = 1.f + (y0 - pcy), wy1 = 1.f - (y1 - pcy);
                int ix0 = (int)x0 * WP, ix1 = (int)x1 * WP;
                int iy0 = (int)y0,      iy1 = (int)y1;
                i00 = ix0 + iy0; i01 = ix0 + iy1; i10 = ix1 + iy0; i11 = ix1 + iy1;
                gg0 = wx0*wy0; gg1 = wx1*wy1; gg2 = wx0*wy1; gg3 = wx1*wy0;
            }

            // gather 4 channels, convert, store A
            {
                float raw[16];
                int ch = (i & 7)*16 + cg*4;
                const float* __restrict__ base = g_xpad + ((size_t)(b*C + ch))*HPWP;
                #pragma unroll
                for (int cc = 0; cc < 4; cc++) {
                    const float* __restrict__ Xp = base + (size_t)cc*HPWP;
                    raw[cc*4+0] = Xp[i00];
                    raw[cc*4+1] = Xp[i11];
                    raw[cc*4+2] = Xp[i01];
                    raw[cc*4+3] = Xp[i10];
                }
                char* st = sm + s*STG;
                float v0 = gg0*raw[0]  + gg1*raw[1]  + gg2*raw[2]  + gg3*raw[3];
                float v1 = gg0*raw[4]  + gg1*raw[5]  + gg2*raw[6]  + gg3*raw[7];
                float v2 = gg0*raw[8]  + gg1*raw[9]  + gg2*raw[10] + gg3*raw[11];
                float v3 = gg0*raw[12] + gg1*raw[13] + gg2*raw[14] + gg3*raw[15];
                __nv_bfloat16 h0 = __float2bfloat16(v0), h1 = __float2bfloat16(v1);
                __nv_bfloat16 h2 = __float2bfloat16(v2), h3 = __float2bfloat16(v3);
                __nv_bfloat16 l0 = __float2bfloat16(v0 - __bfloat162float(h0));
                __nv_bfloat16 l1 = __float2bfloat16(v1 - __bfloat162float(h1));
                __nv_bfloat16 l2 = __float2bfloat16(v2 - __bfloat162float(h2));
                __nv_bfloat16 l3 = __float2bfloat16(v3 - __bfloat162float(h3));
                uint32_t hp0 = (uint32_t)*(unsigned short*)&h0 | ((uint32_t)*(unsigned short*)&h1 << 16);
                uint32_t hp1 = (uint32_t)*(unsigned short*)&h2 | ((uint32_t)*(unsigned short*)&h3 << 16);
                uint32_t lp0 = (uint32_t)*(unsigned short*)&l0 | ((uint32_t)*(unsigned short*)&l1 << 16);
                uint32_t lp1 = (uint32_t)*(unsigned short*)&l2 | ((uint32_t)*(unsigned short*)&l3 << 16);
                *(uint2*)(st + S_AH + pos*ARS + cg*8) = make_uint2(hp0, hp1);
                *(uint2*)(st + S_AL + pos*ARS + cg*8) = make_uint2(lp0, lp1);
            }

            CP_WAIT0();
            mbar_arrive(mb + s*8);               // full[s], release
            if (++s == NST) { s = 0; wrap++; }
        }
    } else {
        // ================= CONSUMER =================
        const int cw = wid - 8;
        const int wm = cw & 1;
        const int wn = cw >> 1;
        const uint32_t aoff = (uint32_t)((wm*32 + (lane & 7) + ((lane >> 3) & 1)*8)*ARS + (lane >> 4)*16);
        const uint32_t boff = (uint32_t)((wn*64 + (lane & 7) + (lane >> 4)*8)*ARS + ((lane >> 3) & 1)*16);

        int s = 0, wrap = 0;
        for (int i = 0; i < NHC; i++) {
            mbar_wait(mb + s*8, wrap & 1);       // full[s], acquire
            const uint32_t stu = sbase + s*STG;

            uint32_t ah[2][4], al[2][4];
            ldsm4(ah[0], stu + S_AH + aoff);
            ldsm4(ah[1], stu + S_AH + aoff + 16*ARS);
            ldsm4(al[0], stu + S_AL + aoff);
            ldsm4(al[1], stu + S_AL + aoff + 16*ARS);
            #pragma unroll
            for (int j = 0; j < 4; j++) {
                uint32_t bh[4], bl[4];
                ldsm4(bh, stu + S_BH + boff + j*16*ARS);
                ldsm4(bl, stu + S_BL + boff + j*16*ARS);
                #pragma unroll
                for (int mi = 0; mi < 2; mi++) {
                    mma_bf16(acc[mi][2*j],   ah[mi], bh);
                    mma_bf16(acc[mi][2*j],   ah[mi], bl);
                    mma_bf16(acc[mi][2*j],   al[mi], bh);
                    mma_bf16(acc[mi][2*j+1], ah[mi], bh + 2);
                    mma_bf16(acc[mi][2*j+1], ah[mi], bl + 2);
                    mma_bf16(acc[mi][2*j+1], al[mi], bh + 2);
                }
            }

            mbar_arrive(mb + (NST+s)*8);         // empty[s] (reads done: regs hold data)
            if (++s == NST) { s = 0; wrap++; }
        }
    }

    __syncthreads();

    // ---- epilogue: transpose via smem; fused BN partial sums ----
    float* sepi = (float*)sm;        // [64 ch][65 pos] fp32 = 16.6 KB
    const int r  = lane >> 2;
    const int tq = lane & 3;
    const int cw = wid - 8;
    for (int qt = 0; qt < 4; qt++) {
        if (wid >= 8 && (cw >> 1) == qt) {
            const int wm = cw & 1;
            #pragma unroll
            for (int mi = 0; mi < 2; mi++) {
                int pos0 = wm*32 + mi*16 + r;
                #pragma unroll
                for (int nt = 0; nt < 8; nt++) {
                    int ch0 = nt*8 + tq*2;
                    sepi[(ch0  )*65 + pos0    ] = acc[mi][nt][0];
                    sepi[(ch0+1)*65 + pos0    ] = acc[mi][nt][1];
                    sepi[(ch0  )*65 + pos0 + 8] = acc[mi][nt][2];
                    sepi[(ch0+1)*65 + pos0 + 8] = acc[mi][nt][3];
                }
            }
        }
        __syncthreads();
        {
            int ri = tid >> 3, j = tid & 7;          // 64 rows x 8 segs of 8
            int o = qt*64 + ri;
            const float* src = sepi + ri*65 + j*8;
            float* dst = out + (((size_t)b*CO + o)*H + h)*W + w0 + j*8;
            float s1 = 0.f, s2 = 0.f;
            #pragma unroll
            for (int k4 = 0; k4 < 2; k4++) {
                float4 v = make_float4(src[k4*4+0], src[k4*4+1], src[k4*4+2], src[k4*4+3]);
                *(float4*)(dst + k4*4) = v;
                s1 += v.x + v.y + v.z + v.w;
                s2 += v.x*v.x + v.y*v.y + v.z*v.z + v.w*v.w;
            }
            // reduce over the 8 j-lanes (contiguous within warp)
            #pragma unroll
            for (int m = 1; m < 8; m <<= 1) {
                s1 += __shfl_xor_sync(0xffffffffu, s1, m);
                s2 += __shfl_xor_sync(0xffffffffu, s2, m);
            }
            if (j == 0) {
                atomicAdd(&g_sums[o], s1);
                atomicAdd(&g_sums[CO + o], s2);
            }
        }
        __syncthreads();
    }
}

// ---------------------------------------------------------------------------
__global__ void bn_apply(float* __restrict__ out,
                         const float* __restrict__ gamma,
                         const float* __restrict__ beta) {
    int idx = blockIdx.x*blockDim.x + threadIdx.x;
    const int total4 = BB*CO*H*W/4;
    if (idx >= total4) return;
    int o = ((idx*4) / (H*W)) % CO;
    const float inv = 1.f / (float)(BB*H*W);
    float mean = g_sums[o] * inv;
    float var  = g_sums[CO + o] * inv - mean*mean;
    float sc = gamma[o] * rsqrtf(var + 1e-5f);
    float sh = beta[o] - mean*sc;
    float4 v = ((float4*)out)[idx];
    v.x = v.x*sc + sh; v.x = v.x >= 0.f ? v.x : 0.1f*v.x;
    v.y = v.y*sc + sh; v.y = v.y >= 0.f ? v.y : 0.1f*v.y;
    v.z = v.z*sc + sh; v.z = v.z >= 0.f ? v.z : 0.1f*v.z;
    v.w = v.w*sc + sh; v.w = v.w >= 0.f ? v.w : 0.1f*v.w;
    ((float4*)out)[idx] = v;
}

// ---------------------------------------------------------------------------
extern "C" void kernel_launch(void* const* d_in, const int* in_sizes, int n_in,
                              void* d_out, int out_size) {
    const float* x      = (const float*)d_in[0];
    const float* p_w    = (const float*)d_in[1];
    const float* p_b    = (const float*)d_in[2];
    const float* w_conv = (const float*)d_in[3];
    const float* gamma  = (const float*)d_in[4];
    const float* beta   = (const float*)d_in[5];
    float* out = (float*)d_out;

    cudaFuncSetAttribute(deform_mma, cudaFuncAttributeMaxDynamicSharedMemorySize, SMEM_DYN);

    pad_kernel    <<<(BB*C*HP*WP + 255)/256, 256>>>(x);
    wprep_kernel  <<<(CO*KTOT + 255)/256, 256>>>(w_conv);
    offconv_kernel<<<BB*H, 128>>>(p_w, p_b);
    deform_mma    <<<dim3(H*2, BB), 512, SMEM_DYN>>>(out);
    bn_apply      <<<(BB*CO*H*W/4 + 255)/256, 256>>>(out, gamma, beta);
}